// round 10
// baseline (speedup 1.0000x reference)
#include <cuda_runtime.h>

#define LCOLS 4096
#define NSTAGES 12
#define RROWS 8
#define NPAIR 4
#define TPB 1024
#define NBATCH 8192

typedef unsigned long long ull;

// ---- packed f32x2 helpers (FFMA2/FMUL2 are PTX-only on sm_103a) ----
__device__ __forceinline__ ull pack2(float a, float b) {
    ull r; asm("mov.b64 %0, {%1, %2};" : "=l"(r) : "f"(a), "f"(b)); return r;
}
__device__ __forceinline__ void unpack2(ull v, float& a, float& b) {
    asm("mov.b64 {%0, %1}, %2;" : "=f"(a), "=f"(b) : "l"(v));
}
__device__ __forceinline__ ull dup2(float a) { return pack2(a, a); }
__device__ __forceinline__ ull mul2(ull a, ull b) {
    ull d; asm("mul.rn.f32x2 %0, %1, %2;" : "=l"(d) : "l"(a), "l"(b)); return d;
}
__device__ __forceinline__ ull fma2(ull a, ull b, ull c) {
    ull d; asm("fma.rn.f32x2 %0, %1, %2, %3;" : "=l"(d) : "l"(a), "l"(b), "l"(c)); return d;
}

// packed butterfly on reg-bit D over 4 regs; weights shared by both packed rows
template <int D>
__device__ __forceinline__ void bfly2(ull Y[NPAIR][4],
                                      const float* w0, const float* w1) {
    #pragma unroll
    for (int c = 0; c < 4; ++c) {
        if (c & D) continue;
        const int ch = c | D;
        const ull W0l = dup2(w0[c]),  W1l = dup2(w1[c]);
        const ull W0h = dup2(w0[ch]), W1h = dup2(w1[ch]);
        #pragma unroll
        for (int p = 0; p < NPAIR; ++p) {
            const ull a = Y[p][c], b = Y[p][ch];
            Y[p][c]  = fma2(W0l, a, mul2(W1l, b));
            Y[p][ch] = fma2(W0h, b, mul2(W1h, a));
        }
    }
}

// swap roles of register bit MC and lane bit ML (half-exchange, 2 shfl / 4 regs)
template <int MC, int ML>
__device__ __forceinline__ void bitswap2(ull* yr, bool lo) {
    #pragma unroll
    for (int c = 0; c < 4; ++c) {
        if (c & MC) continue;
        const int ch = c | MC;
        ull send = lo ? yr[ch] : yr[c];
        ull recv = __shfl_xor_sync(0xffffffffu, send, ML);
        if (lo) yr[ch] = recv; else yr[c] = recv;
    }
}

// y[j] <- W[s][j][0]*y[j] + W[s][j][1]*y[j ^ (1<<s)]
// TPB=1024, ONE smem round trip total:
// Phase 1 (stages 0..6): regs j[0:1] -> swapA j[2:3] -> swapB j[4:5] -> swapC j[6];
//   store to smem at phys(j) = j ^ (j9<<2) ^ (j10<<3) ^ (j11<<4).
// Phase 2 (stages 7..11): gather regs=j[7:8], lane bits 2,3,4 = j9,j10,j11.
//   Stages 7,8 in-register; bit-swap chain brings j9, j10, j11 into reg bit 0
//   for stages 9,10,11. Direct global store.
__global__ __launch_bounds__(TPB, 1)
void butterfly_kernel(const float* __restrict__ x,
                      const float* __restrict__ W,
                      float* __restrict__ out)
{
    extern __shared__ float sm[];   // RROWS * LCOLS floats = 128 KB
    const int tid  = threadIdx.x;
    const int row0 = blockIdx.x * RROWS;
    const int l    = tid & 31;
    const int w    = tid >> 5;
    const int j0   = tid * 4;
    const bool lo1  = (l & 1) == 0;
    const bool lo2  = (l & 2) == 0;
    const bool lo4  = (l & 4) == 0;
    const bool lo8  = (l & 8) == 0;
    const bool lo16 = (l & 16) == 0;

    ull Y[NPAIR][4];

    // ---- load 8 rows x 4 contiguous cols, pack row-pairs ----
    #pragma unroll
    for (int p = 0; p < NPAIR; ++p) {
        float4 a0 = __ldg(reinterpret_cast<const float4*>(
            x + (size_t)(row0 + 2 * p) * LCOLS + j0));
        float4 a1 = __ldg(reinterpret_cast<const float4*>(
            x + (size_t)(row0 + 2 * p + 1) * LCOLS + j0));
        Y[p][0] = pack2(a0.x, a1.x); Y[p][1] = pack2(a0.y, a1.y);
        Y[p][2] = pack2(a0.z, a1.z); Y[p][3] = pack2(a0.w, a1.w);
    }

    float w0[4], w1[4];

    // ---- stages 0,1 : regs = j[0:1], weights 2x float4 contiguous ----
    #pragma unroll
    for (int s = 0; s < 2; ++s) {
        const float4* wp = reinterpret_cast<const float4*>(
            W + (size_t)s * (LCOLS * 2) + j0 * 2);
        float4 wA = __ldg(wp), wB = __ldg(wp + 1);
        w0[0]=wA.x; w1[0]=wA.y; w0[1]=wA.z; w1[1]=wA.w;
        w0[2]=wB.x; w1[2]=wB.y; w0[3]=wB.z; w1[3]=wB.w;
        if (s == 0) bfly2<1>(Y, w0, w1); else bfly2<2>(Y, w0, w1);
    }

    // ---- swap A : regs = j[2:3] ; stages 2,3 ----
    #pragma unroll
    for (int p = 0; p < NPAIR; ++p) {
        bitswap2<1, 1>(Y[p], lo1);
        bitswap2<2, 2>(Y[p], lo2);
    }
    const int jA = (l & 3) + ((l >> 2) & 7) * 16 + w * 128;   // j = jA + 4c
    #pragma unroll
    for (int s = 2; s < 4; ++s) {
        #pragma unroll
        for (int c = 0; c < 4; ++c) {
            const float2 ww = __ldg(reinterpret_cast<const float2*>(
                W + (size_t)s * (LCOLS * 2) + 2 * (jA + 4 * c)));
            w0[c] = ww.x; w1[c] = ww.y;
        }
        if (s == 2) bfly2<1>(Y, w0, w1); else bfly2<2>(Y, w0, w1);
    }

    // ---- swap B : regs = j[4:5] ; stages 4,5 ----
    #pragma unroll
    for (int p = 0; p < NPAIR; ++p) {
        bitswap2<1, 4>(Y[p], lo4);
        bitswap2<2, 8>(Y[p], lo8);
    }
    const int jB = (l & 15) + ((l >> 4) & 1) * 64 + w * 128;  // j = jB + 16c
    #pragma unroll
    for (int s = 4; s < 6; ++s) {
        #pragma unroll
        for (int c = 0; c < 4; ++c) {
            const float2 ww = __ldg(reinterpret_cast<const float2*>(
                W + (size_t)s * (LCOLS * 2) + 2 * (jB + 16 * c)));
            w0[c] = ww.x; w1[c] = ww.y;
        }
        if (s == 4) bfly2<1>(Y, w0, w1); else bfly2<2>(Y, w0, w1);
    }

    // ---- swap C : reg bit0 = j[6] (bit1 stays j[5]) ; stage 6 ----
    #pragma unroll
    for (int p = 0; p < NPAIR; ++p)
        bitswap2<1, 16>(Y[p], lo16);
    const int jC = (l & 15) + ((l >> 4) & 1) * 16 + w * 128;
    // j(c) = jC + (c&1)*64 + ((c>>1)&1)*32 ; warp bits w = j7..j11
    {
        #pragma unroll
        for (int c = 0; c < 4; ++c) {
            const int jb = jC + ((c & 1) << 6) + (((c >> 1) & 1) << 5);
            const float2 ww = __ldg(reinterpret_cast<const float2*>(
                W + (size_t)6 * (LCOLS * 2) + 2 * jb));
            w0[c] = ww.x; w1[c] = ww.y;
        }
        bfly2<1>(Y, w0, w1);
    }

    // ---- store to smem at phys(j) = j ^ (j9<<2) ^ (j10<<3) ^ (j11<<4) ----
    {
        // j9,j10,j11 are warp bits here (w bits 2,3,4)
        const int px = (((w >> 2) & 1) << 2) | (((w >> 3) & 1) << 3)
                     | (((w >> 4) & 1) << 4);
        int sj[4];
        #pragma unroll
        for (int c = 0; c < 4; ++c)
            sj[c] = (jC + ((c & 1) << 6) + (((c >> 1) & 1) << 5)) ^ px;
        #pragma unroll
        for (int p = 0; p < NPAIR; ++p)
            #pragma unroll
            for (int c = 0; c < 4; ++c) {
                float a, b;
                unpack2(Y[p][c], a, b);
                sm[(2 * p) * LCOLS + sj[c]] = a;
                sm[(2 * p + 1) * LCOLS + sj[c]] = b;
            }
    }
    __syncthreads();

    // ---- phase 2: stages 7..11, single gather ----
    // lanes: l0,l1 = j0,j1 ; l2,l3,l4 = j9,j10,j11 ; warps: j2..j6 ; regs: j7,j8
    const int l2b = (l >> 2) & 1, l3b = (l >> 3) & 1, l4b = (l >> 4) & 1;
    const int base2 = (l & 3) | (w << 2) | (l2b << 9) | (l3b << 10) | (l4b << 11);
    const int pb2 = base2 ^ (l2b << 2) ^ (l3b << 3) ^ (l4b << 4);   // phys

    ull V[NPAIR][4];
    #pragma unroll
    for (int p = 0; p < NPAIR; ++p)
        #pragma unroll
        for (int c = 0; c < 4; ++c) {
            const int off = pb2 + ((c & 1) << 7) + (((c >> 1) & 1) << 8);
            const float a = sm[(2 * p) * LCOLS + off];
            const float b = sm[(2 * p + 1) * LCOLS + off];
            V[p][c] = pack2(a, b);
        }

    // stages 7,8 : in-register (c0 = j7, c1 = j8)
    #pragma unroll
    for (int s = 7; s < 9; ++s) {
        #pragma unroll
        for (int c = 0; c < 4; ++c) {
            const int jb = base2 + ((c & 1) << 7) + (((c >> 1) & 1) << 8);
            const float2 ww = __ldg(reinterpret_cast<const float2*>(
                W + (size_t)s * (LCOLS * 2) + 2 * jb));
            w0[c] = ww.x; w1[c] = ww.y;
        }
        if (s == 7) bfly2<1>(V, w0, w1); else bfly2<2>(V, w0, w1);
    }

    // swap: c0 (j7) <-> lane bit2 (j9) ; stage 9 in-register
    #pragma unroll
    for (int p = 0; p < NPAIR; ++p) bitswap2<1, 4>(V[p], lo4);
    const int b9 = (l & 3) | (w << 2) | (l2b << 7) | (l3b << 10) | (l4b << 11);
    {
        #pragma unroll
        for (int c = 0; c < 4; ++c) {
            const int jb = b9 + ((c & 1) << 9) + (((c >> 1) & 1) << 8);
            const float2 ww = __ldg(reinterpret_cast<const float2*>(
                W + (size_t)9 * (LCOLS * 2) + 2 * jb));
            w0[c] = ww.x; w1[c] = ww.y;
        }
        bfly2<1>(V, w0, w1);
    }

    // swap: c0 (j9) <-> lane bit3 (j10) ; stage 10 in-register
    #pragma unroll
    for (int p = 0; p < NPAIR; ++p) bitswap2<1, 8>(V[p], lo8);
    const int b10 = (l & 3) | (w << 2) | (l2b << 7) | (l3b << 9) | (l4b << 11);
    {
        #pragma unroll
        for (int c = 0; c < 4; ++c) {
            const int jb = b10 + ((c & 1) << 10) + (((c >> 1) & 1) << 8);
            const float2 ww = __ldg(reinterpret_cast<const float2*>(
                W + (size_t)10 * (LCOLS * 2) + 2 * jb));
            w0[c] = ww.x; w1[c] = ww.y;
        }
        bfly2<1>(V, w0, w1);
    }

    // swap: c0 (j10) <-> lane bit4 (j11) ; stage 11 in-register
    #pragma unroll
    for (int p = 0; p < NPAIR; ++p) bitswap2<1, 16>(V[p], lo16);
    const int b11m = (l & 3) | (w << 2) | (l2b << 7) | (l3b << 9) | (l4b << 10);
    {
        #pragma unroll
        for (int c = 0; c < 4; ++c) {
            const int jb = b11m + ((c & 1) << 11) + (((c >> 1) & 1) << 8);
            const float2 ww = __ldg(reinterpret_cast<const float2*>(
                W + (size_t)11 * (LCOLS * 2) + 2 * jb));
            w0[c] = ww.x; w1[c] = ww.y;
        }
        bfly2<1>(V, w0, w1);
    }

    // ---- direct global store (final layout: c0=j11, c1=j8) ----
    #pragma unroll
    for (int p = 0; p < NPAIR; ++p) {
        float* op0 = out + (size_t)(row0 + 2 * p) * LCOLS + b11m;
        float* op1 = out + (size_t)(row0 + 2 * p + 1) * LCOLS + b11m;
        #pragma unroll
        for (int c = 0; c < 4; ++c) {
            const int off = ((c & 1) << 11) + (((c >> 1) & 1) << 8);
            float a, b;
            unpack2(V[p][c], a, b);
            op0[off] = a;
            op1[off] = b;
        }
    }
}

extern "C" void kernel_launch(void* const* d_in, const int* in_sizes, int n_in,
                              void* d_out, int out_size) {
    const float* x;
    const float* W;
    if (in_sizes[0] == NSTAGES * LCOLS * 2) {   // W has 98304 elements
        W = (const float*)d_in[0];
        x = (const float*)d_in[1];
    } else {
        x = (const float*)d_in[0];
        W = (const float*)d_in[1];
    }
    float* out = (float*)d_out;

    const int smem_bytes = RROWS * LCOLS * sizeof(float);  // 128 KB
    cudaFuncSetAttribute(butterfly_kernel,
                         cudaFuncAttributeMaxDynamicSharedMemorySize, smem_bytes);
    butterfly_kernel<<<NBATCH / RROWS, TPB, smem_bytes>>>(x, W, out);
}

// round 11
// speedup vs baseline: 1.4935x; 1.4935x over previous
#include <cuda_runtime.h>

#define LCOLS 4096
#define NSTAGES 12
#define RROWS 8
#define NPAIR 4
#define TPB 1024
#define NBATCH 8192

typedef unsigned long long ull;

// ---- packed f32x2 helpers (FFMA2/FMUL2 are PTX-only on sm_103a) ----
__device__ __forceinline__ ull pack2(float a, float b) {
    ull r; asm("mov.b64 %0, {%1, %2};" : "=l"(r) : "f"(a), "f"(b)); return r;
}
__device__ __forceinline__ void unpack2(ull v, float& a, float& b) {
    asm("mov.b64 {%0, %1}, %2;" : "=f"(a), "=f"(b) : "l"(v));
}
__device__ __forceinline__ ull dup2(float a) { return pack2(a, a); }
__device__ __forceinline__ ull mul2(ull a, ull b) {
    ull d; asm("mul.rn.f32x2 %0, %1, %2;" : "=l"(d) : "l"(a), "l"(b)); return d;
}
__device__ __forceinline__ ull fma2(ull a, ull b, ull c) {
    ull d; asm("fma.rn.f32x2 %0, %1, %2, %3;" : "=l"(d) : "l"(a), "l"(b), "l"(c)); return d;
}

// packed butterfly on reg-bit D over 4 regs; weights shared by both packed rows
template <int D>
__device__ __forceinline__ void bfly2(ull Y[NPAIR][4],
                                      const float* w0, const float* w1) {
    #pragma unroll
    for (int c = 0; c < 4; ++c) {
        if (c & D) continue;
        const int ch = c | D;
        const ull W0l = dup2(w0[c]),  W1l = dup2(w1[c]);
        const ull W0h = dup2(w0[ch]), W1h = dup2(w1[ch]);
        #pragma unroll
        for (int p = 0; p < NPAIR; ++p) {
            const ull a = Y[p][c], b = Y[p][ch];
            Y[p][c]  = fma2(W0l, a, mul2(W1l, b));
            Y[p][ch] = fma2(W0h, b, mul2(W1h, a));
        }
    }
}

// swap roles of register bit MC and lane bit ML (half-exchange, 2 shfl / 4 regs)
template <int MC, int ML>
__device__ __forceinline__ void bitswap2(ull* yr, bool lo) {
    #pragma unroll
    for (int c = 0; c < 4; ++c) {
        if (c & MC) continue;
        const int ch = c | MC;
        ull send = lo ? yr[ch] : yr[c];
        ull recv = __shfl_xor_sync(0xffffffffu, send, ML);
        if (lo) yr[ch] = recv; else yr[c] = recv;
    }
}

// shared-memory physical swizzle: bank bit 4 ^= address bit 11
__device__ __forceinline__ int phys(int a) {
    return a ^ (((a >> 11) & 1) << 4);
}

// y[j] <- W[s][j][0]*y[j] + W[s][j][1]*y[j ^ (1<<s)]
// TPB=1024: thread owns 4 cols (2 reg bits), row-pairs packed in f32x2,
// smem accessed as 64-bit words (one ull = one column of a row-pair).
// Phase 1 (stages 0..6): regs j[0:1] -> swapA j[2:3] -> swapB j[4:5] -> swapC j[6].
// Round 1 (stages 7..8): smem gather regs=j[7:8], in-place writeback.
// Round 2 (stages 9..11): smem gather regs=j[9:10], stage 11 shfl mask 16,
// direct global store (64B runs; lanes carry low j bits for all global access).
__global__ __launch_bounds__(TPB, 1)
void butterfly_kernel(const float* __restrict__ x,
                      const float* __restrict__ W,
                      float* __restrict__ out)
{
    extern __shared__ ull sm2[];   // NPAIR * LCOLS ulls = 128 KB
    const int tid  = threadIdx.x;
    const int row0 = blockIdx.x * RROWS;
    const int l    = tid & 31;
    const int w    = tid >> 5;
    const int j0   = tid * 4;
    const bool lo1  = (l & 1) == 0;
    const bool lo2  = (l & 2) == 0;
    const bool lo4  = (l & 4) == 0;
    const bool lo8  = (l & 8) == 0;
    const bool lo16 = (l & 16) == 0;

    ull Y[NPAIR][4];

    // ---- load 8 rows x 4 contiguous cols, pack row-pairs ----
    #pragma unroll
    for (int p = 0; p < NPAIR; ++p) {
        float4 a0 = __ldg(reinterpret_cast<const float4*>(
            x + (size_t)(row0 + 2 * p) * LCOLS + j0));
        float4 a1 = __ldg(reinterpret_cast<const float4*>(
            x + (size_t)(row0 + 2 * p + 1) * LCOLS + j0));
        Y[p][0] = pack2(a0.x, a1.x); Y[p][1] = pack2(a0.y, a1.y);
        Y[p][2] = pack2(a0.z, a1.z); Y[p][3] = pack2(a0.w, a1.w);
    }

    float w0[4], w1[4];

    // ---- stages 0,1 : regs = j[0:1], weights 2x float4 contiguous ----
    #pragma unroll
    for (int s = 0; s < 2; ++s) {
        const float4* wp = reinterpret_cast<const float4*>(
            W + (size_t)s * (LCOLS * 2) + j0 * 2);
        float4 wA = __ldg(wp), wB = __ldg(wp + 1);
        w0[0]=wA.x; w1[0]=wA.y; w0[1]=wA.z; w1[1]=wA.w;
        w0[2]=wB.x; w1[2]=wB.y; w0[3]=wB.z; w1[3]=wB.w;
        if (s == 0) bfly2<1>(Y, w0, w1); else bfly2<2>(Y, w0, w1);
    }

    // ---- swap A : regs = j[2:3] ; stages 2,3 ----
    #pragma unroll
    for (int p = 0; p < NPAIR; ++p) {
        bitswap2<1, 1>(Y[p], lo1);
        bitswap2<2, 2>(Y[p], lo2);
    }
    const int jA = (l & 3) + ((l >> 2) & 7) * 16 + w * 128;   // j = jA + 4c
    #pragma unroll
    for (int s = 2; s < 4; ++s) {
        #pragma unroll
        for (int c = 0; c < 4; ++c) {
            const float2 ww = __ldg(reinterpret_cast<const float2*>(
                W + (size_t)s * (LCOLS * 2) + 2 * (jA + 4 * c)));
            w0[c] = ww.x; w1[c] = ww.y;
        }
        if (s == 2) bfly2<1>(Y, w0, w1); else bfly2<2>(Y, w0, w1);
    }

    // ---- swap B : regs = j[4:5] ; stages 4,5 ----
    #pragma unroll
    for (int p = 0; p < NPAIR; ++p) {
        bitswap2<1, 4>(Y[p], lo4);
        bitswap2<2, 8>(Y[p], lo8);
    }
    const int jB = (l & 15) + ((l >> 4) & 1) * 64 + w * 128;  // j = jB + 16c
    #pragma unroll
    for (int s = 4; s < 6; ++s) {
        #pragma unroll
        for (int c = 0; c < 4; ++c) {
            const float2 ww = __ldg(reinterpret_cast<const float2*>(
                W + (size_t)s * (LCOLS * 2) + 2 * (jB + 16 * c)));
            w0[c] = ww.x; w1[c] = ww.y;
        }
        if (s == 4) bfly2<1>(Y, w0, w1); else bfly2<2>(Y, w0, w1);
    }

    // ---- swap C : reg bit0 = j[6] (bit1 stays j[5]) ; stage 6 ----
    #pragma unroll
    for (int p = 0; p < NPAIR; ++p)
        bitswap2<1, 16>(Y[p], lo16);
    const int jC = (l & 15) + ((l >> 4) & 1) * 16 + w * 128;
    // j(c) = jC + (c&1)*64 + ((c>>1)&1)*32
    {
        #pragma unroll
        for (int c = 0; c < 4; ++c) {
            const int jb = jC + ((c & 1) << 6) + (((c >> 1) & 1) << 5);
            const float2 ww = __ldg(reinterpret_cast<const float2*>(
                W + (size_t)6 * (LCOLS * 2) + 2 * jb));
            w0[c] = ww.x; w1[c] = ww.y;
        }
        bfly2<1>(Y, w0, w1);
    }

    // ---- store packed columns to smem at phys(j), 64-bit STS ----
    {
        int sj[4];
        #pragma unroll
        for (int c = 0; c < 4; ++c)
            sj[c] = phys(jC + ((c & 1) << 6) + (((c >> 1) & 1) << 5));
        #pragma unroll
        for (int p = 0; p < NPAIR; ++p)
            #pragma unroll
            for (int c = 0; c < 4; ++c)
                sm2[p * LCOLS + sj[c]] = Y[p][c];
    }
    __syncthreads();

    // ---- round 1 : stages 7,8 (regs = j[7:8]) ----
    // lanes = j[0:4]; warp bits = (j5, j6, j9, j10, j11)
    const int base1 = l + (w & 1) * 32 + ((w >> 1) & 1) * 64
                    + ((w >> 2) & 1) * 512 + ((w >> 3) & 1) * 1024
                    + ((w >> 4) & 1) * 2048;            // j = base1 + 128c
    const int pb1 = phys(base1);                        // bit11 const, no carry
    {
        ull V[NPAIR][4];
        #pragma unroll
        for (int p = 0; p < NPAIR; ++p)
            #pragma unroll
            for (int c = 0; c < 4; ++c)
                V[p][c] = sm2[p * LCOLS + pb1 + 128 * c];

        #pragma unroll
        for (int s = 7; s < 9; ++s) {
            #pragma unroll
            for (int c = 0; c < 4; ++c) {
                const float2 ww = __ldg(reinterpret_cast<const float2*>(
                    W + (size_t)s * (LCOLS * 2) + 2 * (base1 + 128 * c)));
                w0[c] = ww.x; w1[c] = ww.y;
            }
            if (s == 7) bfly2<1>(V, w0, w1); else bfly2<2>(V, w0, w1);
        }

        // in-place writeback (each element owned by exactly this thread)
        #pragma unroll
        for (int p = 0; p < NPAIR; ++p)
            #pragma unroll
            for (int c = 0; c < 4; ++c)
                sm2[p * LCOLS + pb1 + 128 * c] = V[p][c];
    }
    __syncthreads();

    // ---- round 2 : stages 9,10 (regs = j[9:10]), stage 11 (lane bit 4) ----
    // lanes = (j0..j3, j11); warp bits = j[4:8]
    const int base2 = (l & 15) + w * 16 + ((l >> 4) & 1) * 2048;  // j = base2 + 512c
    const int pb2 = base2 ^ (((l >> 4) & 1) << 4);                // phys, no carry
    {
        ull V[NPAIR][4];
        #pragma unroll
        for (int p = 0; p < NPAIR; ++p)
            #pragma unroll
            for (int c = 0; c < 4; ++c)
                V[p][c] = sm2[p * LCOLS + pb2 + 512 * c];

        #pragma unroll
        for (int s = 9; s < 11; ++s) {
            #pragma unroll
            for (int c = 0; c < 4; ++c) {
                const float2 ww = __ldg(reinterpret_cast<const float2*>(
                    W + (size_t)s * (LCOLS * 2) + 2 * (base2 + 512 * c)));
                w0[c] = ww.x; w1[c] = ww.y;
            }
            if (s == 9) bfly2<1>(V, w0, w1); else bfly2<2>(V, w0, w1);
        }

        // stage 11 : partner is lane^16 (j11)
        #pragma unroll
        for (int c = 0; c < 4; ++c) {
            const float2 ww = __ldg(reinterpret_cast<const float2*>(
                W + (size_t)11 * (LCOLS * 2) + 2 * (base2 + 512 * c)));
            w0[c] = ww.x; w1[c] = ww.y;
        }
        #pragma unroll
        for (int c = 0; c < 4; ++c) {
            const ull W0 = dup2(w0[c]), W1 = dup2(w1[c]);
            #pragma unroll
            for (int p = 0; p < NPAIR; ++p) {
                ull pr = __shfl_xor_sync(0xffffffffu, V[p][c], 16);
                V[p][c] = fma2(W0, V[p][c], mul2(W1, pr));
            }
        }

        // direct global store: per c, lanes 0-15 / 16-31 each cover 64B runs
        #pragma unroll
        for (int p = 0; p < NPAIR; ++p) {
            float* op0 = out + (size_t)(row0 + 2 * p) * LCOLS + base2;
            float* op1 = out + (size_t)(row0 + 2 * p + 1) * LCOLS + base2;
            #pragma unroll
            for (int c = 0; c < 4; ++c) {
                float a, b;
                unpack2(V[p][c], a, b);
                op0[512 * c] = a;
                op1[512 * c] = b;
            }
        }
    }
}

extern "C" void kernel_launch(void* const* d_in, const int* in_sizes, int n_in,
                              void* d_out, int out_size) {
    const float* x;
    const float* W;
    if (in_sizes[0] == NSTAGES * LCOLS * 2) {   // W has 98304 elements
        W = (const float*)d_in[0];
        x = (const float*)d_in[1];
    } else {
        x = (const float*)d_in[0];
        W = (const float*)d_in[1];
    }
    float* out = (float*)d_out;

    const int smem_bytes = NPAIR * LCOLS * sizeof(ull);  // 128 KB
    cudaFuncSetAttribute(butterfly_kernel,
                         cudaFuncAttributeMaxDynamicSharedMemorySize, smem_bytes);
    butterfly_kernel<<<NBATCH / RROWS, TPB, smem_bytes>>>(x, W, out);
}